// round 1
// baseline (speedup 1.0000x reference)
#include <cuda_runtime.h>
#include <math.h>

// Problem constants
#define NE    32          // experts
#define KTOP  4           // top-k
#define HDIM  1024        // hidden
#define IDIM  512         // intermediate
#define TTOK  4096        // tokens (B*S)
#define CAP   1024        // per-expert capacity

// Scratch (device globals: allocation-free per harness rules)
__device__ int   g_count[NE];
__device__ int   g_tok[NE * CAP];
__device__ float g_wt[NE * CAP];
__device__ float g_act[(size_t)NE * CAP * IDIM];     // 64 MB: silu(gate)*up per expert slot
__device__ float g_shact[(size_t)TTOK * IDIM];       // 8 MB: shared-expert activations

__global__ void zero_counts_kernel() {
    if (threadIdx.x < NE) g_count[threadIdx.x] = 0;
}

// ---------------------------------------------------------------------------
// Router: logits = x @ gate_w^T, softmax, top-4 (ties -> lowest index, matches
// jax top_k), renormalize over the top-4, atomic dispatch into capacity lists.
// One block per token, 128 threads (4 warps x 8 experts each).
// ---------------------------------------------------------------------------
__global__ void router_kernel(const float* __restrict__ x,
                              const float* __restrict__ gw) {
    const int t = blockIdx.x;
    __shared__ float xs[HDIM];
    __shared__ float logits[NE];

    const float* xr = x + (size_t)t * HDIM;
    for (int i = threadIdx.x; i < HDIM; i += 128) xs[i] = xr[i];
    __syncthreads();

    const int warp = threadIdx.x >> 5;
    const int lane = threadIdx.x & 31;
    for (int i = 0; i < 8; i++) {
        const int e = warp * 8 + i;
        const float* w = gw + (size_t)e * HDIM;
        float s = 0.f;
        #pragma unroll 8
        for (int j = lane; j < HDIM; j += 32) s += xs[j] * w[j];
        #pragma unroll
        for (int o = 16; o > 0; o >>= 1) s += __shfl_down_sync(0xffffffffu, s, o);
        if (lane == 0) logits[e] = s;
    }
    __syncthreads();

    if (threadIdx.x == 0) {
        float mx = logits[0];
        #pragma unroll
        for (int e = 1; e < NE; e++) mx = fmaxf(mx, logits[e]);
        float p[NE];
        #pragma unroll
        for (int e = 0; e < NE; e++) p[e] = expf(logits[e] - mx);

        int   idx[KTOP];
        float pv[KTOP];
        float psum = 0.f;
        bool used[NE];
        #pragma unroll
        for (int e = 0; e < NE; e++) used[e] = false;
        for (int k = 0; k < KTOP; k++) {
            float best = -1.f; int bi = 0;
            for (int e = 0; e < NE; e++)
                if (!used[e] && p[e] > best) { best = p[e]; bi = e; }
            used[bi] = true; idx[k] = bi; pv[k] = best; psum += best;
        }
        const float inv = 1.f / psum;
        for (int k = 0; k < KTOP; k++) {
            const int e = idx[k];
            const int pos = atomicAdd(&g_count[e], 1);
            if (pos < CAP) {
                g_tok[e * CAP + pos] = t;
                g_wt[e * CAP + pos]  = pv[k] * inv;
            }
        }
    }
}

// ---------------------------------------------------------------------------
// Gate-up GEMM with fused silu-gate:  act[m, n] = silu(A@Wg)[m,n] * (A@Wu)[m,n]
// W is [K=HDIM][2*IDIM] row-major; gate cols [0,IDIM), up cols [IDIM,2*IDIM).
// 64x64 output tile, BK=16, 256 threads, 4x4 micro-tile (dual accumulators).
// GATHER: A rows gathered via token list (expert path) vs identity (shared).
// ---------------------------------------------------------------------------
template <bool GATHER>
__global__ void __launch_bounds__(256)
gateup_kernel(const float* __restrict__ X,
              const float* __restrict__ W,
              int Mrows) {
    const int e = GATHER ? blockIdx.z : 0;
    int n_e;
    const int* tok = nullptr;
    if (GATHER) { n_e = min(g_count[e], CAP); tok = g_tok + e * CAP; }
    else        { n_e = Mrows; }
    const int m0 = blockIdx.y * 64;
    if (m0 >= n_e) return;
    const int n0 = blockIdx.x * 64;

    const float* We = W + (size_t)e * HDIM * (2 * IDIM);
    float* act = GATHER ? (g_act + (size_t)e * CAP * IDIM) : g_shact;

    __shared__ float As[64][17];
    __shared__ float Bg[16][64];
    __shared__ float Bu[16][64];

    const int tid = threadIdx.x;
    const int tx = tid & 15, ty = tid >> 4;
    const int ar = tid >> 2, ak = (tid & 3) << 2;   // A: 64 rows x (4 float4)
    const int br = tid >> 4, bc = (tid & 15) << 2;  // B: 16 rows x (16 float4)

    const bool avalid = (m0 + ar) < n_e;
    const float* arow;
    if (GATHER) arow = X + (size_t)(avalid ? tok[m0 + ar] : 0) * HDIM;
    else        arow = X + (size_t)(avalid ? (m0 + ar) : 0) * HDIM;

    float cg[4][4] = {}, cu[4][4] = {};

    for (int k0 = 0; k0 < HDIM; k0 += 16) {
        float4 av = make_float4(0.f, 0.f, 0.f, 0.f);
        if (avalid) av = *(const float4*)(arow + k0 + ak);
        As[ar][ak + 0] = av.x; As[ar][ak + 1] = av.y;
        As[ar][ak + 2] = av.z; As[ar][ak + 3] = av.w;
        const float* wr = We + (size_t)(k0 + br) * (2 * IDIM) + n0 + bc;
        *(float4*)&Bg[br][bc] = *(const float4*)(wr);
        *(float4*)&Bu[br][bc] = *(const float4*)(wr + IDIM);
        __syncthreads();

        #pragma unroll
        for (int kk = 0; kk < 16; kk++) {
            float a[4];
            #pragma unroll
            for (int i = 0; i < 4; i++) a[i] = As[ty * 4 + i][kk];
            const float4 bg = *(const float4*)&Bg[kk][tx * 4];
            const float4 bu = *(const float4*)&Bu[kk][tx * 4];
            #pragma unroll
            for (int i = 0; i < 4; i++) {
                cg[i][0] += a[i] * bg.x; cg[i][1] += a[i] * bg.y;
                cg[i][2] += a[i] * bg.z; cg[i][3] += a[i] * bg.w;
                cu[i][0] += a[i] * bu.x; cu[i][1] += a[i] * bu.y;
                cu[i][2] += a[i] * bu.z; cu[i][3] += a[i] * bu.w;
            }
        }
        __syncthreads();
    }

    #pragma unroll
    for (int i = 0; i < 4; i++) {
        const int row = m0 + ty * 4 + i;
        if (row < n_e) {
            float4 o;
            float g, u;
            g = cg[i][0]; u = cu[i][0]; o.x = (g / (1.f + expf(-g))) * u;
            g = cg[i][1]; u = cu[i][1]; o.y = (g / (1.f + expf(-g))) * u;
            g = cg[i][2]; u = cu[i][2]; o.z = (g / (1.f + expf(-g))) * u;
            g = cg[i][3]; u = cu[i][3]; o.w = (g / (1.f + expf(-g))) * u;
            *(float4*)(act + (size_t)row * IDIM + n0 + tx * 4) = o;
        }
    }
}

// ---------------------------------------------------------------------------
// Down GEMM: C = A[n_e, IDIM] @ W[IDIM, HDIM].
// SCATTER: epilogue atomicAdd(out[token], weight * C[row]) (expert path)
// else:    dense store to out (shared path; also initializes poisoned out).
// ---------------------------------------------------------------------------
template <bool SCATTER>
__global__ void __launch_bounds__(256)
down_kernel(const float* __restrict__ W,
            float* __restrict__ out,
            int Mrows) {
    const int e = SCATTER ? blockIdx.z : 0;
    int n_e;
    const int* tok = nullptr;
    const float* wts = nullptr;
    const float* A;
    if (SCATTER) {
        n_e = min(g_count[e], CAP);
        tok = g_tok + e * CAP;
        wts = g_wt + e * CAP;
        A = g_act + (size_t)e * CAP * IDIM;
    } else {
        n_e = Mrows;
        A = g_shact;
    }
    const int m0 = blockIdx.y * 64;
    if (m0 >= n_e) return;
    const int n0 = blockIdx.x * 64;
    const float* We = SCATTER ? (W + (size_t)e * IDIM * HDIM) : W;

    __shared__ float As[64][17];
    __shared__ float Bs[16][64];

    const int tid = threadIdx.x;
    const int tx = tid & 15, ty = tid >> 4;
    const int ar = tid >> 2, ak = (tid & 3) << 2;
    const int br = tid >> 4, bc = (tid & 15) << 2;

    const float* arow = A + (size_t)(m0 + ar) * IDIM;  // tile-aligned, in-bounds
    float c[4][4] = {};

    for (int k0 = 0; k0 < IDIM; k0 += 16) {
        const float4 av = *(const float4*)(arow + k0 + ak);
        As[ar][ak + 0] = av.x; As[ar][ak + 1] = av.y;
        As[ar][ak + 2] = av.z; As[ar][ak + 3] = av.w;
        *(float4*)&Bs[br][bc] = *(const float4*)(We + (size_t)(k0 + br) * HDIM + n0 + bc);
        __syncthreads();

        #pragma unroll
        for (int kk = 0; kk < 16; kk++) {
            float a[4];
            #pragma unroll
            for (int i = 0; i < 4; i++) a[i] = As[ty * 4 + i][kk];
            const float4 b = *(const float4*)&Bs[kk][tx * 4];
            #pragma unroll
            for (int i = 0; i < 4; i++) {
                c[i][0] += a[i] * b.x; c[i][1] += a[i] * b.y;
                c[i][2] += a[i] * b.z; c[i][3] += a[i] * b.w;
            }
        }
        __syncthreads();
    }

    #pragma unroll
    for (int i = 0; i < 4; i++) {
        const int row = m0 + ty * 4 + i;
        if (row < n_e) {
            if (SCATTER) {
                const int   t = tok[row];
                const float w = wts[row];
                float* op = out + (size_t)t * HDIM + n0 + tx * 4;
                atomicAdd(op + 0, w * c[i][0]);
                atomicAdd(op + 1, w * c[i][1]);
                atomicAdd(op + 2, w * c[i][2]);
                atomicAdd(op + 3, w * c[i][3]);
            } else {
                float4 o;
                o.x = c[i][0]; o.y = c[i][1]; o.z = c[i][2]; o.w = c[i][3];
                *(float4*)(out + (size_t)row * HDIM + n0 + tx * 4) = o;
            }
        }
    }
}

extern "C" void kernel_launch(void* const* d_in, const int* in_sizes, int n_in,
                              void* d_out, int out_size) {
    const float* x   = (const float*)d_in[0];  // [2,2048,1024]
    const float* gw  = (const float*)d_in[1];  // [32,1024]
    const float* wgu = (const float*)d_in[2];  // [32,1024,1024]
    const float* wd  = (const float*)d_in[3];  // [32,512,1024]
    const float* sgu = (const float*)d_in[4];  // [1024,1024]
    const float* sd  = (const float*)d_in[5];  // [512,1024]
    float* out = (float*)d_out;                // [2,2048,1024] f32

    (void)in_sizes; (void)n_in; (void)out_size;

    zero_counts_kernel<<<1, 32>>>();
    router_kernel<<<TTOK, 128>>>(x, gw);

    // Expert gate-up (gathered A, fused silu-mul)
    gateup_kernel<true ><<<dim3(IDIM / 64, CAP / 64, NE), 256>>>(x, wgu, 0);
    // Shared gate-up
    gateup_kernel<false><<<dim3(IDIM / 64, TTOK / 64, 1), 256>>>(x, sgu, TTOK);

    // Shared down: dense write (initializes out) — must precede expert atomics
    down_kernel<false><<<dim3(HDIM / 64, TTOK / 64, 1), 256>>>(sd, out, TTOK);
    // Expert down: weighted atomic scatter-add
    down_kernel<true ><<<dim3(HDIM / 64, CAP / 64, NE), 256>>>(wd, out, 0);
}

// round 5
// speedup vs baseline: 2.9242x; 2.9242x over previous
#include <cuda_runtime.h>
#include <math.h>
#include <stdint.h>

#define NE    32
#define KTOP  4
#define HDIM  1024
#define IDIM  512
#define TTOK  4096
#define CAP   1024

// ---------------- device scratch (no allocations allowed) ----------------
__device__ int   g_count[NE];
__device__ int   g_tok[NE * CAP];
__device__ int   g_e4[TTOK * KTOP];
__device__ int   g_s4[TTOK * KTOP];
__device__ float g_w4[TTOK * KTOP];
__device__ float g_act[(size_t)NE * CAP * IDIM];     // silu(g)*u per slot
__device__ float g_shact[(size_t)TTOK * IDIM];       // shared activations
__device__ float g_dbuf[(size_t)NE * CAP * HDIM];    // per-slot down output

// ---------------- helpers ----------------
__device__ __forceinline__ uint32_t to_tf32(float x) {
    uint32_t u;
    asm("cvt.rna.tf32.f32 %0, %1;" : "=r"(u) : "f"(x));
    return u;
}
// m16n8k8 tf32 MMA. A frag: a0(g,t) a1(g+8,t) a2(g,t+4) a3(g+8,t+4);
// B frag: b0(k=t,n=g) b1(k=t+4,n=g); C: c0(g,2t) c1(g,2t+1) c2(g+8,2t) c3(g+8,2t+1)
__device__ __forceinline__ void mma8(float* c, const uint32_t* a,
                                     uint32_t b0, uint32_t b1) {
    asm volatile(
        "mma.sync.aligned.m16n8k8.row.col.f32.tf32.tf32.f32 "
        "{%0,%1,%2,%3}, {%4,%5,%6,%7}, {%8,%9}, {%0,%1,%2,%3};"
        : "+f"(c[0]), "+f"(c[1]), "+f"(c[2]), "+f"(c[3])
        : "r"(a[0]), "r"(a[1]), "r"(a[2]), "r"(a[3]), "r"(b0), "r"(b1));
}

// ---------------- router ----------------
__global__ void zero_counts_kernel() {
    if (threadIdx.x < NE) g_count[threadIdx.x] = 0;
}

__global__ void router_kernel(const float* __restrict__ x,
                              const float* __restrict__ gw) {
    const int t = blockIdx.x;
    __shared__ float xs[HDIM];
    __shared__ float logits[NE];
    const float* xr = x + (size_t)t * HDIM;
    for (int i = threadIdx.x; i < HDIM; i += 128) xs[i] = xr[i];
    __syncthreads();

    const int warp = threadIdx.x >> 5, lane = threadIdx.x & 31;
    for (int i = 0; i < 8; i++) {
        const int e = warp * 8 + i;
        const float* w = gw + (size_t)e * HDIM;
        float s = 0.f;
        #pragma unroll 8
        for (int j = lane; j < HDIM; j += 32) s += xs[j] * w[j];
        #pragma unroll
        for (int o = 16; o > 0; o >>= 1) s += __shfl_down_sync(0xffffffffu, s, o);
        if (lane == 0) logits[e] = s;
    }
    __syncthreads();

    if (threadIdx.x == 0) {
        float mx = logits[0];
        #pragma unroll
        for (int e = 1; e < NE; e++) mx = fmaxf(mx, logits[e]);
        float p[NE];
        #pragma unroll
        for (int e = 0; e < NE; e++) p[e] = expf(logits[e] - mx);
        int idx[KTOP]; float pv[KTOP]; float psum = 0.f;
        bool used[NE];
        #pragma unroll
        for (int e = 0; e < NE; e++) used[e] = false;
        for (int k = 0; k < KTOP; k++) {
            float best = -1.f; int bi = 0;
            for (int e = 0; e < NE; e++)
                if (!used[e] && p[e] > best) { best = p[e]; bi = e; }
            used[bi] = true; idx[k] = bi; pv[k] = best; psum += best;
        }
        const float inv = 1.f / psum;
        for (int k = 0; k < KTOP; k++) {
            const int e = idx[k];
            const int pos = atomicAdd(&g_count[e], 1);
            if (pos < CAP) g_tok[e * CAP + pos] = t;
            g_e4[t * KTOP + k] = e;
            g_s4[t * KTOP + k] = pos;
            g_w4[t * KTOP + k] = pv[k] * inv;
        }
    }
}

// ---------------- gate-up (tf32 mma.sync, fused silu) ----------------
// block tile M=128 x N=64(gate)+64(up); 8 warps (4 M x 2 N), warp 32x32 each
// of gate/up; K chunks of 32.
#define GU_AS 36   // A smem row stride (floats):  (36r+c)%32 = (4r+c) distinct
#define GU_BS 136  // B smem row stride: 136%32=8 -> (8k+n) distinct

template <bool EXPERT>
__global__ void __launch_bounds__(256)
gu_mma(const float* __restrict__ X, const float* __restrict__ Wgu) {
    const int e = EXPERT ? blockIdx.z : 0;
    const int n_e = EXPERT ? min(g_count[e], CAP) : TTOK;
    const int m0 = blockIdx.y * 128;
    if (m0 >= n_e) return;
    const int n0 = blockIdx.x * 64;

    __shared__ uint32_t As[128 * GU_AS];
    __shared__ uint32_t Bs[32 * GU_BS];
    __shared__ const float* rowp[128];

    const int tid = threadIdx.x;
    const int wid = tid >> 5, lane = tid & 31;
    const int g = lane >> 2, tig = lane & 3;
    const int wm = wid & 3, wn = wid >> 2;

    for (int r = tid; r < 128; r += 256) {
        const int gr = m0 + r;
        const float* p = nullptr;
        if (gr < n_e) p = X + (size_t)(EXPERT ? g_tok[e * CAP + gr] : gr) * HDIM;
        rowp[r] = p;
    }
    const float* W = EXPERT ? Wgu + (size_t)e * HDIM * (2 * IDIM) : Wgu;
    float* actb = EXPERT ? g_act + (size_t)e * CAP * IDIM : g_shact;
    __syncthreads();

    float cg[2][4][4], cu[2][4][4];
    #pragma unroll
    for (int a = 0; a < 2; a++)
        #pragma unroll
        for (int b = 0; b < 4; b++)
            #pragma unroll
            for (int d = 0; d < 4; d++) { cg[a][b][d] = 0.f; cu[a][b][d] = 0.f; }

    // staging mappings (per thread: 4 float4 of A, 4 float4 of B)
    const int aj = tid & 7;             // float4 index within a 32-float A row
    const int at = tid >> 3;            // A row base (per i: row = i*32 + at)
    const int bq = tid & 31;            // B float4 col index (0..15 gate, 16..31 up)
    const int bt = tid >> 5;            // B k base (per i: k = i*8 + bt)
    const int bcol = (bq < 16) ? (n0 + bq * 4) : (IDIM + n0 + (bq - 16) * 4);
    const int bsc  = (bq < 16) ? (bq * 4) : (64 + (bq - 16) * 4);

    float4 ra[4], rb[4];
    // LDG chunk k0 into registers
    #define GU_LDG(k0) do { \
        _Pragma("unroll") \
        for (int i = 0; i < 4; i++) { \
            const float* p = rowp[i * 32 + at]; \
            ra[i] = p ? *(const float4*)(p + (k0) + aj * 4) \
                      : make_float4(0.f, 0.f, 0.f, 0.f); \
        } \
        _Pragma("unroll") \
        for (int i = 0; i < 4; i++) \
            rb[i] = *(const float4*)(W + (size_t)((k0) + i * 8 + bt) * (2 * IDIM) + bcol); \
    } while (0)

    GU_LDG(0);

    for (int c = 0; c < HDIM / 32; c++) {
        // convert + store to smem
        #pragma unroll
        for (int i = 0; i < 4; i++) {
            uint4 t = make_uint4(to_tf32(ra[i].x), to_tf32(ra[i].y),
                                 to_tf32(ra[i].z), to_tf32(ra[i].w));
            *(uint4*)&As[(i * 32 + at) * GU_AS + aj * 4] = t;
        }
        #pragma unroll
        for (int i = 0; i < 4; i++) {
            uint4 t = make_uint4(to_tf32(rb[i].x), to_tf32(rb[i].y),
                                 to_tf32(rb[i].z), to_tf32(rb[i].w));
            *(uint4*)&Bs[(i * 8 + bt) * GU_BS + bsc] = t;
        }
        __syncthreads();

        if (c + 1 < HDIM / 32) GU_LDG((c + 1) * 32);

        #pragma unroll
        for (int kf = 0; kf < 4; kf++) {
            uint32_t a[2][4];
            #pragma unroll
            for (int mf = 0; mf < 2; mf++) {
                const int rb_ = wm * 32 + mf * 16 + g;
                const int cb  = kf * 8 + tig;
                a[mf][0] = As[rb_ * GU_AS + cb];
                a[mf][1] = As[(rb_ + 8) * GU_AS + cb];
                a[mf][2] = As[rb_ * GU_AS + cb + 4];
                a[mf][3] = As[(rb_ + 8) * GU_AS + cb + 4];
            }
            #pragma unroll
            for (int nf = 0; nf < 4; nf++) {
                const int nc = wn * 32 + nf * 8 + g;
                const int kr = kf * 8 + tig;
                const uint32_t bg0 = Bs[kr * GU_BS + nc];
                const uint32_t bg1 = Bs[(kr + 4) * GU_BS + nc];
                const uint32_t bu0 = Bs[kr * GU_BS + 64 + nc];
                const uint32_t bu1 = Bs[(kr + 4) * GU_BS + 64 + nc];
                mma8(cg[0][nf], a[0], bg0, bg1);
                mma8(cg[1][nf], a[1], bg0, bg1);
                mma8(cu[0][nf], a[0], bu0, bu1);
                mma8(cu[1][nf], a[1], bu0, bu1);
            }
        }
        __syncthreads();
    }
    #undef GU_LDG

    // epilogue: silu(gate)*up
    #pragma unroll
    for (int mf = 0; mf < 2; mf++) {
        #pragma unroll
        for (int nf = 0; nf < 4; nf++) {
            const int row0 = m0 + wm * 32 + mf * 16 + g;
            const int col  = n0 + wn * 32 + nf * 8 + tig * 2;
            if (row0 < n_e) {
                float gv, uv; float2 o;
                gv = cg[mf][nf][0]; uv = cu[mf][nf][0]; o.x = gv / (1.f + __expf(-gv)) * uv;
                gv = cg[mf][nf][1]; uv = cu[mf][nf][1]; o.y = gv / (1.f + __expf(-gv)) * uv;
                *(float2*)(actb + (size_t)row0 * IDIM + col) = o;
            }
            if (row0 + 8 < n_e) {
                float gv, uv; float2 o;
                gv = cg[mf][nf][2]; uv = cu[mf][nf][2]; o.x = gv / (1.f + __expf(-gv)) * uv;
                gv = cg[mf][nf][3]; uv = cu[mf][nf][3]; o.y = gv / (1.f + __expf(-gv)) * uv;
                *(float2*)(actb + (size_t)(row0 + 8) * IDIM + col) = o;
            }
        }
    }
}

// ---------------- down (tf32 mma.sync) ----------------
// block tile M=128 x N=64; warp 32x32; K=512 in chunks of 32.
#define DN_AS 36
#define DN_BS 72   // 72%32=8 -> (8k+n) distinct

template <bool EXPERT>
__global__ void __launch_bounds__(256)
dn_mma(const float* __restrict__ Wd, float* __restrict__ out) {
    const int e = EXPERT ? blockIdx.z : 0;
    const int n_e = EXPERT ? min(g_count[e], CAP) : TTOK;
    const int m0 = blockIdx.y * 128;
    if (m0 >= n_e) return;
    const int n0 = blockIdx.x * 64;

    __shared__ uint32_t As[128 * DN_AS];
    __shared__ uint32_t Bs[32 * DN_BS];

    const int tid = threadIdx.x;
    const int wid = tid >> 5, lane = tid & 31;
    const int g = lane >> 2, tig = lane & 3;
    const int wm = wid & 3, wn = wid >> 2;

    const float* actb = EXPERT ? g_act + (size_t)e * CAP * IDIM : g_shact;
    const float* W = EXPERT ? Wd + (size_t)e * IDIM * HDIM : Wd;

    float cc[2][4][4];
    #pragma unroll
    for (int a = 0; a < 2; a++)
        #pragma unroll
        for (int b = 0; b < 4; b++)
            #pragma unroll
            for (int d = 0; d < 4; d++) cc[a][b][d] = 0.f;

    const int aj = tid & 7;
    const int at = tid >> 3;
    const int bq = tid & 15;   // B: 16 float4 per k-row (64 cols)
    const int bt = tid >> 4;   // per i: k = i*16 + bt

    float4 ra[4], rb[2];
    #define DN_LDG(k0) do { \
        _Pragma("unroll") \
        for (int i = 0; i < 4; i++) \
            ra[i] = *(const float4*)(actb + (size_t)(m0 + i * 32 + at) * IDIM + (k0) + aj * 4); \
        _Pragma("unroll") \
        for (int i = 0; i < 2; i++) \
            rb[i] = *(const float4*)(W + (size_t)((k0) + i * 16 + bt) * HDIM + n0 + bq * 4); \
    } while (0)

    DN_LDG(0);

    for (int c = 0; c < IDIM / 32; c++) {
        #pragma unroll
        for (int i = 0; i < 4; i++) {
            uint4 t = make_uint4(to_tf32(ra[i].x), to_tf32(ra[i].y),
                                 to_tf32(ra[i].z), to_tf32(ra[i].w));
            *(uint4*)&As[(i * 32 + at) * DN_AS + aj * 4] = t;
        }
        #pragma unroll
        for (int i = 0; i < 2; i++) {
            uint4 t = make_uint4(to_tf32(rb[i].x), to_tf32(rb[i].y),
                                 to_tf32(rb[i].z), to_tf32(rb[i].w));
            *(uint4*)&Bs[(i * 16 + bt) * DN_BS + bq * 4] = t;
        }
        __syncthreads();

        if (c + 1 < IDIM / 32) DN_LDG((c + 1) * 32);

        #pragma unroll
        for (int kf = 0; kf < 4; kf++) {
            uint32_t a[2][4];
            #pragma unroll
            for (int mf = 0; mf < 2; mf++) {
                const int rb_ = wm * 32 + mf * 16 + g;
                const int cb  = kf * 8 + tig;
                a[mf][0] = As[rb_ * DN_AS + cb];
                a[mf][1] = As[(rb_ + 8) * DN_AS + cb];
                a[mf][2] = As[rb_ * DN_AS + cb + 4];
                a[mf][3] = As[(rb_ + 8) * DN_AS + cb + 4];
            }
            #pragma unroll
            for (int nf = 0; nf < 4; nf++) {
                const int nc = wn * 32 + nf * 8 + g;
                const int kr = kf * 8 + tig;
                const uint32_t b0 = Bs[kr * DN_BS + nc];
                const uint32_t b1 = Bs[(kr + 4) * DN_BS + nc];
                mma8(cc[0][nf], a[0], b0, b1);
                mma8(cc[1][nf], a[1], b0, b1);
            }
        }
        __syncthreads();
    }
    #undef DN_LDG

    #pragma unroll
    for (int mf = 0; mf < 2; mf++) {
        #pragma unroll
        for (int nf = 0; nf < 4; nf++) {
            const int row0 = m0 + wm * 32 + mf * 16 + g;
            const int col  = n0 + wn * 32 + nf * 8 + tig * 2;
            if (row0 < n_e) {
                float* dst = EXPERT ? (g_dbuf + ((size_t)e * CAP + row0) * HDIM + col)
                                    : (out + (size_t)row0 * HDIM + col);
                *(float2*)dst = make_float2(cc[mf][nf][0], cc[mf][nf][1]);
            }
            if (row0 + 8 < n_e) {
                float* dst = EXPERT ? (g_dbuf + ((size_t)e * CAP + row0 + 8) * HDIM + col)
                                    : (out + (size_t)(row0 + 8) * HDIM + col);
                *(float2*)dst = make_float2(cc[mf][nf][2], cc[mf][nf][3]);
            }
        }
    }
}

// ---------------- combine: out[t] += sum_k w_k * dbuf[e_k, s_k] ----------------
__global__ void __launch_bounds__(256)
combine_kernel(float* __restrict__ out) {
    const int t = blockIdx.x;
    const int i = threadIdx.x;              // 256 float4 per token row
    float4 acc = ((const float4*)out)[(size_t)t * 256 + i];
    #pragma unroll
    for (int k = 0; k < KTOP; k++) {
        const int e = g_e4[t * KTOP + k];
        const int s = g_s4[t * KTOP + k];
        const float w = g_w4[t * KTOP + k];
        if (s < CAP) {
            const float4 v = ((const float4*)g_dbuf)[((size_t)e * CAP + s) * (HDIM / 4) + i];
            acc.x += w * v.x; acc.y += w * v.y; acc.z += w * v.z; acc.w += w * v.w;
        }
    }
    ((float4*)out)[(size_t)t * 256 + i] = acc;
}

extern "C" void kernel_launch(void* const* d_in, const int* in_sizes, int n_in,
                              void* d_out, int out_size) {
    const float* x   = (const float*)d_in[0];
    const float* gw  = (const float*)d_in[1];
    const float* wgu = (const float*)d_in[2];
    const float* wd  = (const float*)d_in[3];
    const float* sgu = (const float*)d_in[4];
    const float* sd  = (const float*)d_in[5];
    float* out = (float*)d_out;
    (void)in_sizes; (void)n_in; (void)out_size;

    zero_counts_kernel<<<1, 32>>>();
    router_kernel<<<TTOK, 128>>>(x, gw);

    // expert gate-up: (N=512/64, M=1024/128, E)
    gu_mma<true ><<<dim3(IDIM / 64, CAP / 128, NE), 256>>>(x, wgu);
    // shared gate-up
    gu_mma<false><<<dim3(IDIM / 64, TTOK / 128, 1), 256>>>(x, sgu);

    // expert down -> dense per-slot buffer (no atomics, deterministic)
    dn_mma<true ><<<dim3(HDIM / 64, CAP / 128, NE), 256>>>(wd, out);
    // shared down -> dense write of out (covers 0xAA poison)
    dn_mma<false><<<dim3(HDIM / 64, TTOK / 128, 1), 256>>>(sd, out);

    combine_kernel<<<TTOK, 256>>>(out);
}

// round 6
// speedup vs baseline: 3.0044x; 1.0274x over previous
#include <cuda_runtime.h>
#include <math.h>
#include <stdint.h>

#define NE    32
#define KTOP  4
#define HDIM  1024
#define IDIM  512
#define TTOK  4096
#define CAP   1024

// ---------------- device scratch ----------------
__device__ int   g_count[NE];
__device__ int   g_tok[NE * CAP];
__device__ int   g_e4[TTOK * KTOP];
__device__ int   g_s4[TTOK * KTOP];
__device__ float g_w4[TTOK * KTOP];
__device__ float g_act[(size_t)NE * CAP * IDIM];
__device__ float g_shact[(size_t)TTOK * IDIM];
__device__ float g_dbuf[(size_t)NE * CAP * HDIM];

// ---------------- helpers ----------------
__device__ __forceinline__ uint32_t to_tf32(float x) {
    uint32_t u;
    asm("cvt.rna.tf32.f32 %0, %1;" : "=r"(u) : "f"(x));
    return u;
}
__device__ __forceinline__ void mma8(float* c, const uint32_t* a,
                                     uint32_t b0, uint32_t b1) {
    asm volatile(
        "mma.sync.aligned.m16n8k8.row.col.f32.tf32.tf32.f32 "
        "{%0,%1,%2,%3}, {%4,%5,%6,%7}, {%8,%9}, {%0,%1,%2,%3};"
        : "+f"(c[0]), "+f"(c[1]), "+f"(c[2]), "+f"(c[3])
        : "r"(a[0]), "r"(a[1]), "r"(a[2]), "r"(a[3]), "r"(b0), "r"(b1));
}

// ---------------- router ----------------
__global__ void zero_counts_kernel() {
    if (threadIdx.x < NE) g_count[threadIdx.x] = 0;
}

__global__ void router_kernel(const float* __restrict__ x,
                              const float* __restrict__ gw) {
    const int t = blockIdx.x;
    __shared__ float xs[HDIM];
    __shared__ float logits[NE];
    const float* xr = x + (size_t)t * HDIM;
    for (int i = threadIdx.x; i < HDIM; i += 128) xs[i] = xr[i];
    __syncthreads();

    const int warp = threadIdx.x >> 5, lane = threadIdx.x & 31;
    for (int i = 0; i < 8; i++) {
        const int e = warp * 8 + i;
        const float* w = gw + (size_t)e * HDIM;
        float s = 0.f;
        #pragma unroll 8
        for (int j = lane; j < HDIM; j += 32) s += xs[j] * w[j];
        #pragma unroll
        for (int o = 16; o > 0; o >>= 1) s += __shfl_down_sync(0xffffffffu, s, o);
        if (lane == 0) logits[e] = s;
    }
    __syncthreads();

    if (threadIdx.x == 0) {
        float mx = logits[0];
        #pragma unroll
        for (int e = 1; e < NE; e++) mx = fmaxf(mx, logits[e]);
        float p[NE];
        #pragma unroll
        for (int e = 0; e < NE; e++) p[e] = expf(logits[e] - mx);
        int idx[KTOP]; float pv[KTOP]; float psum = 0.f;
        bool used[NE];
        #pragma unroll
        for (int e = 0; e < NE; e++) used[e] = false;
        for (int k = 0; k < KTOP; k++) {
            float best = -1.f; int bi = 0;
            for (int e = 0; e < NE; e++)
                if (!used[e] && p[e] > best) { best = p[e]; bi = e; }
            used[bi] = true; idx[k] = bi; pv[k] = best; psum += best;
        }
        const float inv = 1.f / psum;
        for (int k = 0; k < KTOP; k++) {
            const int e = idx[k];
            const int pos = atomicAdd(&g_count[e], 1);
            if (pos < CAP) g_tok[e * CAP + pos] = t;
            g_e4[t * KTOP + k] = e;
            g_s4[t * KTOP + k] = pos;
            g_w4[t * KTOP + k] = pv[k] * inv;
        }
    }
}

// ---------------- GEMM common layout constants ----------------
// A smem: 128 rows x 16 k-words, stride 20 (20g mod 32 distinct -> conflict-free)
// B smem: 16 k-rows x 128 n-words, stride 136 (== 8 mod 32, proven layout)
#define T_AS 20
#define T_BS 136

// ---------------- gate-up (tf32 mma.sync, m64 warp tile, fused silu) -------
// block: 128 thr (4 warps, 2M x 2N). tile M=128, N=64 gate + 64 up.
// warp: m64 x (n32 gate + n32 up). K chunks of 16.
template <bool EXPERT>
__global__ void __launch_bounds__(128)
gu_mma(const float* __restrict__ X, const float* __restrict__ Wgu) {
    const int e = EXPERT ? blockIdx.z : 0;
    const int n_e = EXPERT ? min(g_count[e], CAP) : TTOK;
    const int m0 = blockIdx.y * 128;
    if (m0 >= n_e) return;
    const int n0 = blockIdx.x * 64;

    __shared__ uint32_t As[128 * T_AS];
    __shared__ uint32_t Bs[16 * T_BS];
    __shared__ const float* rowp[128];

    const int tid = threadIdx.x;
    const int wid = tid >> 5, lane = tid & 31;
    const int g = lane >> 2, tig = lane & 3;
    const int wm = wid & 1, wn = wid >> 1;

    if (tid < 128) {
        const int gr = m0 + tid;
        const float* p = nullptr;
        if (gr < n_e) p = X + (size_t)(EXPERT ? g_tok[e * CAP + gr] : gr) * HDIM;
        rowp[tid] = p;
    }
    const float* W = EXPERT ? Wgu + (size_t)e * HDIM * (2 * IDIM) : Wgu;
    float* actb = EXPERT ? g_act + (size_t)e * CAP * IDIM : g_shact;
    __syncthreads();

    float cg[4][4][4], cu[4][4][4];
    #pragma unroll
    for (int a = 0; a < 4; a++)
        #pragma unroll
        for (int b = 0; b < 4; b++)
            #pragma unroll
            for (int d = 0; d < 4; d++) { cg[a][b][d] = 0.f; cu[a][b][d] = 0.f; }

    // staging: A per thread 4 rows (i*32 + tid>>2), colgroup (tid&3)*4
    const int ar = tid >> 2, ac = (tid & 3) * 4;
    // B per thread 4 k-rows (i*4 + tid>>5), col float4 (tid&31)
    const int bk = tid >> 5, bq = tid & 31;
    const int bgcol = (bq < 16) ? (n0 + bq * 4) : (IDIM + n0 + (bq - 16) * 4);
    const int bsc   = bq * 4;

    float4 ra[4], rb[4];
    #define GU_LDG(k0) do { \
        _Pragma("unroll") \
        for (int i = 0; i < 4; i++) { \
            const float* p = rowp[i * 32 + ar]; \
            ra[i] = p ? *(const float4*)(p + (k0) + ac) \
                      : make_float4(0.f, 0.f, 0.f, 0.f); \
        } \
        _Pragma("unroll") \
        for (int i = 0; i < 4; i++) \
            rb[i] = *(const float4*)(W + (size_t)((k0) + i * 4 + bk) * (2 * IDIM) + bgcol); \
    } while (0)

    GU_LDG(0);

    for (int c = 0; c < HDIM / 16; c++) {
        #pragma unroll
        for (int i = 0; i < 4; i++) {
            uint4 t = make_uint4(to_tf32(ra[i].x), to_tf32(ra[i].y),
                                 to_tf32(ra[i].z), to_tf32(ra[i].w));
            *(uint4*)&As[(i * 32 + ar) * T_AS + ac] = t;
        }
        #pragma unroll
        for (int i = 0; i < 4; i++) {
            uint4 t = make_uint4(to_tf32(rb[i].x), to_tf32(rb[i].y),
                                 to_tf32(rb[i].z), to_tf32(rb[i].w));
            *(uint4*)&Bs[(i * 4 + bk) * T_BS + bsc] = t;
        }
        __syncthreads();

        if (c + 1 < HDIM / 16) GU_LDG((c + 1) * 16);

        #pragma unroll
        for (int kf = 0; kf < 2; kf++) {
            uint32_t a[4][4];
            #pragma unroll
            for (int mf = 0; mf < 4; mf++) {
                const int rr = wm * 64 + mf * 16 + g;
                const int cb = kf * 8 + tig;
                a[mf][0] = As[rr * T_AS + cb];
                a[mf][1] = As[(rr + 8) * T_AS + cb];
                a[mf][2] = As[rr * T_AS + cb + 4];
                a[mf][3] = As[(rr + 8) * T_AS + cb + 4];
            }
            #pragma unroll
            for (int nf = 0; nf < 4; nf++) {
                const int ncg = wn * 32 + nf * 8 + g;
                const int kr  = kf * 8 + tig;
                const uint32_t bg0 = Bs[kr * T_BS + ncg];
                const uint32_t bg1 = Bs[(kr + 4) * T_BS + ncg];
                const uint32_t bu0 = Bs[kr * T_BS + 64 + ncg];
                const uint32_t bu1 = Bs[(kr + 4) * T_BS + 64 + ncg];
                #pragma unroll
                for (int mf = 0; mf < 4; mf++) {
                    mma8(cg[mf][nf], a[mf], bg0, bg1);
                    mma8(cu[mf][nf], a[mf], bu0, bu1);
                }
            }
        }
        __syncthreads();
    }
    #undef GU_LDG

    // epilogue: silu(gate)*up
    #pragma unroll
    for (int mf = 0; mf < 4; mf++) {
        #pragma unroll
        for (int nf = 0; nf < 4; nf++) {
            const int row0 = m0 + wm * 64 + mf * 16 + g;
            const int col  = n0 + wn * 32 + nf * 8 + tig * 2;
            if (row0 < n_e) {
                float gv, uv; float2 o;
                gv = cg[mf][nf][0]; uv = cu[mf][nf][0]; o.x = gv / (1.f + __expf(-gv)) * uv;
                gv = cg[mf][nf][1]; uv = cu[mf][nf][1]; o.y = gv / (1.f + __expf(-gv)) * uv;
                *(float2*)(actb + (size_t)row0 * IDIM + col) = o;
            }
            if (row0 + 8 < n_e) {
                float gv, uv; float2 o;
                gv = cg[mf][nf][2]; uv = cu[mf][nf][2]; o.x = gv / (1.f + __expf(-gv)) * uv;
                gv = cg[mf][nf][3]; uv = cu[mf][nf][3]; o.y = gv / (1.f + __expf(-gv)) * uv;
                *(float2*)(actb + (size_t)(row0 + 8) * IDIM + col) = o;
            }
        }
    }
}

// ---------------- down (tf32 mma.sync, m64 x n64 warp tile) ----------------
// block: 128 thr (4 warps, 2M x 2N). tile M=128 x N=128. K chunks of 16.
template <bool EXPERT>
__global__ void __launch_bounds__(128)
dn_mma(const float* __restrict__ Wd, float* __restrict__ out) {
    const int e = EXPERT ? blockIdx.z : 0;
    const int n_e = EXPERT ? min(g_count[e], CAP) : TTOK;
    const int m0 = blockIdx.y * 128;
    if (m0 >= n_e) return;
    const int n0 = blockIdx.x * 128;

    __shared__ uint32_t As[128 * T_AS];
    __shared__ uint32_t Bs[16 * T_BS];

    const int tid = threadIdx.x;
    const int wid = tid >> 5, lane = tid & 31;
    const int g = lane >> 2, tig = lane & 3;
    const int wm = wid & 1, wn = wid >> 1;

    const float* actb = EXPERT ? g_act + (size_t)e * CAP * IDIM : g_shact;
    const float* W = EXPERT ? Wd + (size_t)e * IDIM * HDIM : Wd;

    float cc[4][8][4];
    #pragma unroll
    for (int a = 0; a < 4; a++)
        #pragma unroll
        for (int b = 0; b < 8; b++)
            #pragma unroll
            for (int d = 0; d < 4; d++) cc[a][b][d] = 0.f;

    const int ar = tid >> 2, ac = (tid & 3) * 4;
    const int bk = tid >> 5, bq = tid & 31;

    float4 ra[4], rb[4];
    #define DN_LDG(k0) do { \
        _Pragma("unroll") \
        for (int i = 0; i < 4; i++) \
            ra[i] = *(const float4*)(actb + (size_t)(m0 + i * 32 + ar) * IDIM + (k0) + ac); \
        _Pragma("unroll") \
        for (int i = 0; i < 4; i++) \
            rb[i] = *(const float4*)(W + (size_t)((k0) + i * 4 + bk) * HDIM + n0 + bq * 4); \
    } while (0)

    DN_LDG(0);

    for (int c = 0; c < IDIM / 16; c++) {
        #pragma unroll
        for (int i = 0; i < 4; i++) {
            uint4 t = make_uint4(to_tf32(ra[i].x), to_tf32(ra[i].y),
                                 to_tf32(ra[i].z), to_tf32(ra[i].w));
            *(uint4*)&As[(i * 32 + ar) * T_AS + ac] = t;
        }
        #pragma unroll
        for (int i = 0; i < 4; i++) {
            uint4 t = make_uint4(to_tf32(rb[i].x), to_tf32(rb[i].y),
                                 to_tf32(rb[i].z), to_tf32(rb[i].w));
            *(uint4*)&Bs[(i * 4 + bk) * T_BS + bq * 4] = t;
        }
        __syncthreads();

        if (c + 1 < IDIM / 16) DN_LDG((c + 1) * 16);

        #pragma unroll
        for (int kf = 0; kf < 2; kf++) {
            uint32_t a[4][4];
            #pragma unroll
            for (int mf = 0; mf < 4; mf++) {
                const int rr = wm * 64 + mf * 16 + g;
                const int cb = kf * 8 + tig;
                a[mf][0] = As[rr * T_AS + cb];
                a[mf][1] = As[(rr + 8) * T_AS + cb];
                a[mf][2] = As[rr * T_AS + cb + 4];
                a[mf][3] = As[(rr + 8) * T_AS + cb + 4];
            }
            #pragma unroll
            for (int nf = 0; nf < 8; nf++) {
                const int nc = wn * 64 + nf * 8 + g;
                const int kr = kf * 8 + tig;
                const uint32_t b0 = Bs[kr * T_BS + nc];
                const uint32_t b1 = Bs[(kr + 4) * T_BS + nc];
                #pragma unroll
                for (int mf = 0; mf < 4; mf++)
                    mma8(cc[mf][nf], a[mf], b0, b1);
            }
        }
        __syncthreads();
    }
    #undef DN_LDG

    #pragma unroll
    for (int mf = 0; mf < 4; mf++) {
        #pragma unroll
        for (int nf = 0; nf < 8; nf++) {
            const int row0 = m0 + wm * 64 + mf * 16 + g;
            const int col  = n0 + wn * 64 + nf * 8 + tig * 2;
            if (row0 < n_e) {
                float* dst = EXPERT ? (g_dbuf + ((size_t)e * CAP + row0) * HDIM + col)
                                    : (out + (size_t)row0 * HDIM + col);
                *(float2*)dst = make_float2(cc[mf][nf][0], cc[mf][nf][1]);
            }
            if (row0 + 8 < n_e) {
                float* dst = EXPERT ? (g_dbuf + ((size_t)e * CAP + row0 + 8) * HDIM + col)
                                    : (out + (size_t)(row0 + 8) * HDIM + col);
                *(float2*)dst = make_float2(cc[mf][nf][2], cc[mf][nf][3]);
            }
        }
    }
}

// ---------------- combine ----------------
__global__ void __launch_bounds__(256)
combine_kernel(float* __restrict__ out) {
    const int t = blockIdx.x;
    const int i = threadIdx.x;
    float4 acc = ((const float4*)out)[(size_t)t * 256 + i];
    #pragma unroll
    for (int k = 0; k < KTOP; k++) {
        const int e = g_e4[t * KTOP + k];
        const int s = g_s4[t * KTOP + k];
        const float w = g_w4[t * KTOP + k];
        if (s < CAP) {
            const float4 v = ((const float4*)g_dbuf)[((size_t)e * CAP + s) * (HDIM / 4) + i];
            acc.x += w * v.x; acc.y += w * v.y; acc.z += w * v.z; acc.w += w * v.w;
        }
    }
    ((float4*)out)[(size_t)t * 256 + i] = acc;
}

extern "C" void kernel_launch(void* const* d_in, const int* in_sizes, int n_in,
                              void* d_out, int out_size) {
    const float* x   = (const float*)d_in[0];
    const float* gw  = (const float*)d_in[1];
    const float* wgu = (const float*)d_in[2];
    const float* wd  = (const float*)d_in[3];
    const float* sgu = (const float*)d_in[4];
    const float* sd  = (const float*)d_in[5];
    float* out = (float*)d_out;
    (void)in_sizes; (void)n_in; (void)out_size;

    zero_counts_kernel<<<1, 32>>>();
    router_kernel<<<TTOK, 128>>>(x, gw);

    // expert gate-up: (N=512/64, M=1024/128, E), 128 threads
    gu_mma<true ><<<dim3(IDIM / 64, CAP / 128, NE), 128>>>(x, wgu);
    gu_mma<false><<<dim3(IDIM / 64, TTOK / 128, 1), 128>>>(x, sgu);

    // down: (N=1024/128, M/128, E)
    dn_mma<true ><<<dim3(HDIM / 128, CAP / 128, NE), 128>>>(wd, out);
    dn_mma<false><<<dim3(HDIM / 128, TTOK / 128, 1), 128>>>(sd, out);

    combine_kernel<<<TTOK, 256>>>(out);
}

// round 7
// speedup vs baseline: 3.0118x; 1.0024x over previous
#include <cuda_runtime.h>
#include <math.h>
#include <stdint.h>

#define NE    32
#define KTOP  4
#define HDIM  1024
#define IDIM  512
#define TTOK  4096
#define CAP   1024

// ---------------- device scratch ----------------
__device__ int   g_count[NE];
__device__ int   g_tok[NE * CAP];
__device__ int   g_e4[TTOK * KTOP];
__device__ int   g_s4[TTOK * KTOP];
__device__ float g_w4[TTOK * KTOP];
__device__ float g_act[(size_t)NE * CAP * IDIM];
__device__ float g_shact[(size_t)TTOK * IDIM];
__device__ float g_dbuf[(size_t)NE * CAP * HDIM];

// ---------------- helpers ----------------
__device__ __forceinline__ uint32_t to_tf32(float x) {
    uint32_t u;
    asm("cvt.rna.tf32.f32 %0, %1;" : "=r"(u) : "f"(x));
    return u;
}
__device__ __forceinline__ uint4 cvt4(float4 v) {
    return make_uint4(to_tf32(v.x), to_tf32(v.y), to_tf32(v.z), to_tf32(v.w));
}
__device__ __forceinline__ void mma8(float* c, const uint32_t* a,
                                     uint32_t b0, uint32_t b1) {
    asm volatile(
        "mma.sync.aligned.m16n8k8.row.col.f32.tf32.tf32.f32 "
        "{%0,%1,%2,%3}, {%4,%5,%6,%7}, {%8,%9}, {%0,%1,%2,%3};"
        : "+f"(c[0]), "+f"(c[1]), "+f"(c[2]), "+f"(c[3])
        : "r"(a[0]), "r"(a[1]), "r"(a[2]), "r"(a[3]), "r"(b0), "r"(b1));
}

// ---------------- router ----------------
__global__ void zero_counts_kernel() {
    if (threadIdx.x < NE) g_count[threadIdx.x] = 0;
}

__global__ void router_kernel(const float* __restrict__ x,
                              const float* __restrict__ gw) {
    const int t = blockIdx.x;
    __shared__ float xs[HDIM];
    __shared__ float logits[NE];
    const float* xr = x + (size_t)t * HDIM;
    for (int i = threadIdx.x; i < HDIM; i += 128) xs[i] = xr[i];
    __syncthreads();

    const int warp = threadIdx.x >> 5, lane = threadIdx.x & 31;
    for (int i = 0; i < 8; i++) {
        const int e = warp * 8 + i;
        const float* w = gw + (size_t)e * HDIM;
        float s = 0.f;
        #pragma unroll 8
        for (int j = lane; j < HDIM; j += 32) s += xs[j] * w[j];
        #pragma unroll
        for (int o = 16; o > 0; o >>= 1) s += __shfl_down_sync(0xffffffffu, s, o);
        if (lane == 0) logits[e] = s;
    }
    __syncthreads();

    if (threadIdx.x == 0) {
        float mx = logits[0];
        #pragma unroll
        for (int e = 1; e < NE; e++) mx = fmaxf(mx, logits[e]);
        float p[NE];
        #pragma unroll
        for (int e = 0; e < NE; e++) p[e] = expf(logits[e] - mx);
        int idx[KTOP]; float pv[KTOP]; float psum = 0.f;
        bool used[NE];
        #pragma unroll
        for (int e = 0; e < NE; e++) used[e] = false;
        for (int k = 0; k < KTOP; k++) {
            float best = -1.f; int bi = 0;
            for (int e = 0; e < NE; e++)
                if (!used[e] && p[e] > best) { best = p[e]; bi = e; }
            used[bi] = true; idx[k] = bi; pv[k] = best; psum += best;
        }
        const float inv = 1.f / psum;
        for (int k = 0; k < KTOP; k++) {
            const int e = idx[k];
            const int pos = atomicAdd(&g_count[e], 1);
            if (pos < CAP) g_tok[e * CAP + pos] = t;
            g_e4[t * KTOP + k] = e;
            g_s4[t * KTOP + k] = pos;
            g_w4[t * KTOP + k] = pv[k] * inv;
        }
    }
}

// ---------------- GEMM layout ----------------
// A smem: 128 rows x 32 k-words, row stride 36 (frag LDS: (4g+tig)%32 distinct)
// B smem: 32 k-rows x 128 n-words, row stride 136 (frag LDS: (8tig+g)%32 distinct)
// Double-buffered: A buf = 4608 words, B buf = 4352 words.
#define ASZ 4608
#define BSZ 4352
#define SMEM_BYTES ((2 * ASZ + 2 * BSZ) * 4)   // 71680

// ---------------- gate-up (tf32 mma.sync, fused silu) ----------------
// 128 thr, 4 warps (2M x 2N). block M=128, N=64 gate + 64 up.
// warp m64 x (n32 gate + n32 up). K chunks of 32, 1 barrier/chunk.
template <bool EXPERT>
__global__ void __launch_bounds__(128)
gu_mma(const float* __restrict__ X, const float* __restrict__ Wgu) {
    const int e = EXPERT ? blockIdx.z : 0;
    const int n_e = EXPERT ? min(g_count[e], CAP) : TTOK;
    const int m0 = blockIdx.y * 128;
    if (m0 >= n_e) return;
    const int n0 = blockIdx.x * 64;

    extern __shared__ __align__(16) char smem[];
    uint32_t* As_ = (uint32_t*)smem;
    uint32_t* Bs_ = (uint32_t*)(smem + 2 * ASZ * 4);

    const int tid = threadIdx.x;
    const int wid = tid >> 5, lane = tid & 31;
    const int g = lane >> 2, tig = lane & 3;
    const int wm = wid & 1, wn = wid >> 1;

    const float* W = EXPERT ? Wgu + (size_t)e * HDIM * (2 * IDIM) : Wgu;
    float* actb = EXPERT ? g_act + (size_t)e * CAP * IDIM : g_shact;

    // A staging: 4 rows per thread (i*32 + tid>>2), half-chunk cols (tid&3)*4
    const int ar = tid >> 2, ac = (tid & 3) * 4;
    const float* arow[4];
    #pragma unroll
    for (int i = 0; i < 4; i++) {
        const int r = m0 + i * 32 + ar;
        const float* p = nullptr;
        if (r < n_e) p = X + (size_t)(EXPERT ? g_tok[e * CAP + r] : r) * HDIM;
        arow[i] = p;
    }
    // B staging: k-rows i*4 + wid per half, col float4 bq
    const int bk = wid, bq = lane;  // bq via tid&31 == lane
    const int bcol = (bq < 16) ? (n0 + bq * 4) : (IDIM + n0 + (bq - 16) * 4);

    float cg[4][4][4], cu[4][4][4];
    #pragma unroll
    for (int a = 0; a < 4; a++)
        #pragma unroll
        for (int b = 0; b < 4; b++)
            #pragma unroll
            for (int d = 0; d < 4; d++) { cg[a][b][d] = 0.f; cu[a][b][d] = 0.f; }

    const int abase = (wm * 64 + g) * 36 + tig;
    const int bbase = tig * 136 + wn * 32 + g;

    float4 ra[4], rb[4];
    #define GU_LDGA(k0) do { \
        _Pragma("unroll") \
        for (int i = 0; i < 4; i++) \
            ra[i] = arow[i] ? *(const float4*)(arow[i] + (k0) + ac) \
                            : make_float4(0.f, 0.f, 0.f, 0.f); \
    } while (0)
    #define GU_LDGB(k0) do { \
        _Pragma("unroll") \
        for (int i = 0; i < 4; i++) \
            rb[i] = *(const float4*)(W + (size_t)((k0) + i * 4 + bk) * (2 * IDIM) + bcol); \
    } while (0)
    #define GU_STS(bufi, h) do { \
        _Pragma("unroll") \
        for (int i = 0; i < 4; i++) \
            *(uint4*)&As_[(bufi) * ASZ + (i * 32 + ar) * 36 + (h) * 16 + ac] = cvt4(ra[i]); \
        _Pragma("unroll") \
        for (int i = 0; i < 4; i++) \
            *(uint4*)&Bs_[(bufi) * BSZ + ((h) * 16 + i * 4 + bk) * 136 + bq * 4] = cvt4(rb[i]); \
    } while (0)
    #define GU_COMP(kf) do { \
        uint32_t a[4][4]; \
        _Pragma("unroll") \
        for (int mf = 0; mf < 4; mf++) { \
            const int o = abase + mf * 576 + (kf) * 8; \
            a[mf][0] = Ab[o]; a[mf][1] = Ab[o + 288]; \
            a[mf][2] = Ab[o + 4]; a[mf][3] = Ab[o + 292]; \
        } \
        _Pragma("unroll") \
        for (int nf = 0; nf < 4; nf++) { \
            const int ob = bbase + (kf) * 1088 + nf * 8; \
            const uint32_t bg0 = Bb[ob], bg1 = Bb[ob + 544]; \
            const uint32_t bu0 = Bb[ob + 64], bu1 = Bb[ob + 608]; \
            _Pragma("unroll") \
            for (int mf = 0; mf < 4; mf++) { \
                mma8(cg[mf][nf], a[mf], bg0, bg1); \
                mma8(cu[mf][nf], a[mf], bu0, bu1); \
            } \
        } \
    } while (0)

    GU_LDGA(0);  GU_LDGB(0);  GU_STS(0, 0);
    GU_LDGA(16); GU_LDGB(16); GU_STS(0, 1);
    __syncthreads();

    const int NC = HDIM / 32;
    for (int c = 0; c < NC; c++) {
        const int buf = c & 1;
        const uint32_t* Ab = As_ + buf * ASZ;
        const uint32_t* Bb = Bs_ + buf * BSZ;
        const bool more = (c + 1 < NC);
        if (more) { GU_LDGA((c + 1) * 32); GU_LDGB((c + 1) * 32); }
        GU_COMP(0); GU_COMP(1);
        if (more) { GU_STS(buf ^ 1, 0); GU_LDGA((c + 1) * 32 + 16); GU_LDGB((c + 1) * 32 + 16); }
        GU_COMP(2); GU_COMP(3);
        if (more) { GU_STS(buf ^ 1, 1); }
        __syncthreads();
    }
    #undef GU_LDGA
    #undef GU_LDGB
    #undef GU_STS
    #undef GU_COMP

    // epilogue: silu(gate)*up
    #pragma unroll
    for (int mf = 0; mf < 4; mf++) {
        #pragma unroll
        for (int nf = 0; nf < 4; nf++) {
            const int row0 = m0 + wm * 64 + mf * 16 + g;
            const int col  = n0 + wn * 32 + nf * 8 + tig * 2;
            if (row0 < n_e) {
                float gv, uv; float2 o;
                gv = cg[mf][nf][0]; uv = cu[mf][nf][0]; o.x = gv / (1.f + __expf(-gv)) * uv;
                gv = cg[mf][nf][1]; uv = cu[mf][nf][1]; o.y = gv / (1.f + __expf(-gv)) * uv;
                *(float2*)(actb + (size_t)row0 * IDIM + col) = o;
            }
            if (row0 + 8 < n_e) {
                float gv, uv; float2 o;
                gv = cg[mf][nf][2]; uv = cu[mf][nf][2]; o.x = gv / (1.f + __expf(-gv)) * uv;
                gv = cg[mf][nf][3]; uv = cu[mf][nf][3]; o.y = gv / (1.f + __expf(-gv)) * uv;
                *(float2*)(actb + (size_t)(row0 + 8) * IDIM + col) = o;
            }
        }
    }
}

// ---------------- down (tf32 mma.sync) ----------------
// 128 thr, 4 warps (2M x 2N). block M=128 x N=128; warp m64 x n64.
// K chunks of 32, 1 barrier/chunk.
template <bool EXPERT>
__global__ void __launch_bounds__(128)
dn_mma(const float* __restrict__ Wd, float* __restrict__ out) {
    const int e = EXPERT ? blockIdx.z : 0;
    const int n_e = EXPERT ? min(g_count[e], CAP) : TTOK;
    const int m0 = blockIdx.y * 128;
    if (m0 >= n_e) return;
    const int n0 = blockIdx.x * 128;

    extern __shared__ __align__(16) char smem[];
    uint32_t* As_ = (uint32_t*)smem;
    uint32_t* Bs_ = (uint32_t*)(smem + 2 * ASZ * 4);

    const int tid = threadIdx.x;
    const int wid = tid >> 5, lane = tid & 31;
    const int g = lane >> 2, tig = lane & 3;
    const int wm = wid & 1, wn = wid >> 1;

    const float* actb = EXPERT ? g_act + (size_t)e * CAP * IDIM : g_shact;
    const float* W = EXPERT ? Wd + (size_t)e * IDIM * HDIM : Wd;

    const int ar = tid >> 2, ac = (tid & 3) * 4;
    const float* arow[4];
    #pragma unroll
    for (int i = 0; i < 4; i++)
        arow[i] = actb + (size_t)(m0 + i * 32 + ar) * IDIM;
    const int bk = wid, bq = lane;

    float cc[4][8][4];
    #pragma unroll
    for (int a = 0; a < 4; a++)
        #pragma unroll
        for (int b = 0; b < 8; b++)
            #pragma unroll
            for (int d = 0; d < 4; d++) cc[a][b][d] = 0.f;

    const int abase = (wm * 64 + g) * 36 + tig;
    const int bbase = tig * 136 + wn * 64 + g;

    float4 ra[4], rb[4];
    #define DN_LDGA(k0) do { \
        _Pragma("unroll") \
        for (int i = 0; i < 4; i++) \
            ra[i] = *(const float4*)(arow[i] + (k0) + ac); \
    } while (0)
    #define DN_LDGB(k0) do { \
        _Pragma("unroll") \
        for (int i = 0; i < 4; i++) \
            rb[i] = *(const float4*)(W + (size_t)((k0) + i * 4 + bk) * HDIM + n0 + bq * 4); \
    } while (0)
    #define DN_STS(bufi, h) do { \
        _Pragma("unroll") \
        for (int i = 0; i < 4; i++) \
            *(uint4*)&As_[(bufi) * ASZ + (i * 32 + ar) * 36 + (h) * 16 + ac] = cvt4(ra[i]); \
        _Pragma("unroll") \
        for (int i = 0; i < 4; i++) \
            *(uint4*)&Bs_[(bufi) * BSZ + ((h) * 16 + i * 4 + bk) * 136 + bq * 4] = cvt4(rb[i]); \
    } while (0)
    #define DN_COMP(kf) do { \
        uint32_t a[4][4]; \
        _Pragma("unroll") \
        for (int mf = 0; mf < 4; mf++) { \
            const int o = abase + mf * 576 + (kf) * 8; \
            a[mf][0] = Ab[o]; a[mf][1] = Ab[o + 288]; \
            a[mf][2] = Ab[o + 4]; a[mf][3] = Ab[o + 292]; \
        } \
        _Pragma("unroll") \
        for (int nf = 0; nf < 8; nf++) { \
            const int ob = bbase + (kf) * 1088 + nf * 8; \
            const uint32_t b0 = Bb[ob], b1 = Bb[ob + 544]; \
            _Pragma("unroll") \
            for (int mf = 0; mf < 4; mf++) \
                mma8(cc[mf][nf], a[mf], b0, b1); \
        } \
    } while (0)

    DN_LDGA(0);  DN_LDGB(0);  DN_STS(0, 0);
    DN_LDGA(16); DN_LDGB(16); DN_STS(0, 1);
    __syncthreads();

    const int NC = IDIM / 32;
    for (int c = 0; c < NC; c++) {
        const int buf = c & 1;
        const uint32_t* Ab = As_ + buf * ASZ;
        const uint32_t* Bb = Bs_ + buf * BSZ;
        const bool more = (c + 1 < NC);
        if (more) { DN_LDGA((c + 1) * 32); DN_LDGB((c + 1) * 32); }
        DN_COMP(0); DN_COMP(1);
        if (more) { DN_STS(buf ^ 1, 0); DN_LDGA((c + 1) * 32 + 16); DN_LDGB((c + 1) * 32 + 16); }
        DN_COMP(2); DN_COMP(3);
        if (more) { DN_STS(buf ^ 1, 1); }
        __syncthreads();
    }
    #undef DN_LDGA
    #undef DN_LDGB
    #undef DN_STS
    #undef DN_COMP

    #pragma unroll
    for (int mf = 0; mf < 4; mf++) {
        #pragma unroll
        for (int nf = 0; nf < 8; nf++) {
            const int row0 = m0 + wm * 64 + mf * 16 + g;
            const int col  = n0 + wn * 64 + nf * 8 + tig * 2;
            if (row0 < n_e) {
                float* dst = EXPERT ? (g_dbuf + ((size_t)e * CAP + row0) * HDIM + col)
                                    : (out + (size_t)row0 * HDIM + col);
                *(float2*)dst = make_float2(cc[mf][nf][0], cc[mf][nf][1]);
            }
            if (row0 + 8 < n_e) {
                float* dst = EXPERT ? (g_dbuf + ((size_t)e * CAP + row0 + 8) * HDIM + col)
                                    : (out + (size_t)(row0 + 8) * HDIM + col);
                *(float2*)dst = make_float2(cc[mf][nf][2], cc[mf][nf][3]);
            }
        }
    }
}

// ---------------- combine ----------------
__global__ void __launch_bounds__(256)
combine_kernel(float* __restrict__ out) {
    const int t = blockIdx.x;
    const int i = threadIdx.x;
    float4 acc = ((const float4*)out)[(size_t)t * 256 + i];
    #pragma unroll
    for (int k = 0; k < KTOP; k++) {
        const int e = g_e4[t * KTOP + k];
        const int s = g_s4[t * KTOP + k];
        const float w = g_w4[t * KTOP + k];
        if (s < CAP) {
            const float4 v = ((const float4*)g_dbuf)[((size_t)e * CAP + s) * (HDIM / 4) + i];
            acc.x += w * v.x; acc.y += w * v.y; acc.z += w * v.z; acc.w += w * v.w;
        }
    }
    ((float4*)out)[(size_t)t * 256 + i] = acc;
}

extern "C" void kernel_launch(void* const* d_in, const int* in_sizes, int n_in,
                              void* d_out, int out_size) {
    const float* x   = (const float*)d_in[0];
    const float* gw  = (const float*)d_in[1];
    const float* wgu = (const float*)d_in[2];
    const float* wd  = (const float*)d_in[3];
    const float* sgu = (const float*)d_in[4];
    const float* sd  = (const float*)d_in[5];
    float* out = (float*)d_out;
    (void)in_sizes; (void)n_in; (void)out_size;

    cudaFuncSetAttribute(gu_mma<true>,  cudaFuncAttributeMaxDynamicSharedMemorySize, SMEM_BYTES);
    cudaFuncSetAttribute(gu_mma<false>, cudaFuncAttributeMaxDynamicSharedMemorySize, SMEM_BYTES);
    cudaFuncSetAttribute(dn_mma<true>,  cudaFuncAttributeMaxDynamicSharedMemorySize, SMEM_BYTES);
    cudaFuncSetAttribute(dn_mma<false>, cudaFuncAttributeMaxDynamicSharedMemorySize, SMEM_BYTES);

    zero_counts_kernel<<<1, 32>>>();
    router_kernel<<<TTOK, 128>>>(x, gw);

    gu_mma<true ><<<dim3(IDIM / 64, CAP / 128, NE), 128, SMEM_BYTES>>>(x, wgu);
    gu_mma<false><<<dim3(IDIM / 64, TTOK / 128, 1), 128, SMEM_BYTES>>>(x, sgu);

    dn_mma<true ><<<dim3(HDIM / 128, CAP / 128, NE), 128, SMEM_BYTES>>>(wd, out);
    dn_mma<false><<<dim3(HDIM / 128, TTOK / 128, 1), 128, SMEM_BYTES>>>(sd, out);

    combine_kernel<<<TTOK, 256>>>(out);
}

// round 8
// speedup vs baseline: 3.0597x; 1.0159x over previous
#include <cuda_runtime.h>
#include <cuda_fp16.h>
#include <math.h>
#include <stdint.h>

#define NE    32
#define KTOP  4
#define HDIM  1024
#define IDIM  512
#define TTOK  4096
#define CAP   1024

// ---------------- device scratch ----------------
__device__ int   g_count[NE];
__device__ int   g_tok[NE * CAP];
__device__ int   g_e4[TTOK * KTOP];
__device__ int   g_s4[TTOK * KTOP];
__device__ float g_w4[TTOK * KTOP];
__device__ float g_act[(size_t)NE * CAP * IDIM];
__device__ float g_shact[(size_t)TTOK * IDIM];
__device__ float g_dbuf[(size_t)NE * CAP * HDIM];

// ---------------- helpers ----------------
__device__ __forceinline__ uint32_t pack2(float lo, float hi) {
    __half2 h = __floats2half2_rn(lo, hi);   // .x = lo -> low 16 bits
    return *(uint32_t*)&h;
}
__device__ __forceinline__ void mma16(float* c, const uint32_t* a,
                                      uint32_t b0, uint32_t b1) {
    asm volatile(
        "mma.sync.aligned.m16n8k16.row.col.f32.f16.f16.f32 "
        "{%0,%1,%2,%3}, {%4,%5,%6,%7}, {%8,%9}, {%0,%1,%2,%3};"
        : "+f"(c[0]), "+f"(c[1]), "+f"(c[2]), "+f"(c[3])
        : "r"(a[0]), "r"(a[1]), "r"(a[2]), "r"(a[3]), "r"(b0), "r"(b1));
}

// ---------------- router ----------------
__global__ void zero_counts_kernel() {
    if (threadIdx.x < NE) g_count[threadIdx.x] = 0;
}

__global__ void router_kernel(const float* __restrict__ x,
                              const float* __restrict__ gw) {
    const int t = blockIdx.x;
    __shared__ float xs[HDIM];
    __shared__ float logits[NE];
    const float* xr = x + (size_t)t * HDIM;
    for (int i = threadIdx.x; i < HDIM; i += 128) xs[i] = xr[i];
    __syncthreads();

    const int warp = threadIdx.x >> 5, lane = threadIdx.x & 31;
    for (int i = 0; i < 8; i++) {
        const int e = warp * 8 + i;
        const float* w = gw + (size_t)e * HDIM;
        float s = 0.f;
        #pragma unroll 8
        for (int j = lane; j < HDIM; j += 32) s += xs[j] * w[j];
        #pragma unroll
        for (int o = 16; o > 0; o >>= 1) s += __shfl_down_sync(0xffffffffu, s, o);
        if (lane == 0) logits[e] = s;
    }
    __syncthreads();

    if (threadIdx.x == 0) {
        float mx = logits[0];
        #pragma unroll
        for (int e = 1; e < NE; e++) mx = fmaxf(mx, logits[e]);
        float p[NE];
        #pragma unroll
        for (int e = 0; e < NE; e++) p[e] = expf(logits[e] - mx);
        int idx[KTOP]; float pv[KTOP]; float psum = 0.f;
        bool used[NE];
        #pragma unroll
        for (int e = 0; e < NE; e++) used[e] = false;
        for (int k = 0; k < KTOP; k++) {
            float best = -1.f; int bi = 0;
            for (int e = 0; e < NE; e++)
                if (!used[e] && p[e] > best) { best = p[e]; bi = e; }
            used[bi] = true; idx[k] = bi; pv[k] = best; psum += best;
        }
        const float inv = 1.f / psum;
        for (int k = 0; k < KTOP; k++) {
            const int e = idx[k];
            const int pos = atomicAdd(&g_count[e], 1);
            if (pos < CAP) g_tok[e * CAP + pos] = t;
            g_e4[t * KTOP + k] = e;
            g_s4[t * KTOP + k] = pos;
            g_w4[t * KTOP + k] = pv[k] * inv;
        }
    }
}

// ---------------- GEMM layout (fp16 packed half2 along K) ----------------
// A smem: 128 rows x 16 kp-words (K=32 as half2), row stride 20
//         frag LDS: (20g+tig)%32 distinct -> conflict-free
// B smem: 16 kp-rows x 128 n-words, row stride 136 ((8tig+g)%32 distinct)
#define ASZ 2560   // 128*20
#define BSZ 2176   // 16*136

// ---------------- gate-up (fp16 mma.sync, fused silu) ----------------
// 128 thr, 4 warps (2M x 2N). block M=128, N=64 gate + 64 up.
// warp m64 x (n32 gate + n32 up). K chunks of 32 (2 kf steps of K=16).
template <bool EXPERT>
__global__ void __launch_bounds__(128)
gu_mma(const float* __restrict__ X, const float* __restrict__ Wgu) {
    const int e = EXPERT ? blockIdx.z : 0;
    const int n_e = EXPERT ? min(g_count[e], CAP) : TTOK;
    const int m0 = blockIdx.y * 128;
    if (m0 >= n_e) return;
    const int n0 = blockIdx.x * 64;

    __shared__ uint32_t As_[2 * ASZ];
    __shared__ uint32_t Bs_[2 * BSZ];

    const int tid = threadIdx.x;
    const int wid = tid >> 5, lane = tid & 31;
    const int g = lane >> 2, tig = lane & 3;
    const int wm = wid & 1, wn = wid >> 1;

    const float* W = EXPERT ? Wgu + (size_t)e * HDIM * (2 * IDIM) : Wgu;
    float* actb = EXPERT ? g_act + (size_t)e * CAP * IDIM : g_shact;

    // A staging: one row per thread
    const float* arow = nullptr;
    {
        const int r = m0 + tid;
        if (r < n_e) arow = X + (size_t)(EXPERT ? g_tok[e * CAP + r] : r) * HDIM;
    }
    // B staging: bk = warp (kp base), bq = lane (n-quad)
    const int bk = wid, bq = lane;
    const int bcol = (bq < 16) ? (n0 + bq * 4) : (IDIM + n0 + (bq - 16) * 4);

    float cg[4][4][4], cu[4][4][4];
    #pragma unroll
    for (int a = 0; a < 4; a++)
        #pragma unroll
        for (int b = 0; b < 4; b++)
            #pragma unroll
            for (int d = 0; d < 4; d++) { cg[a][b][d] = 0.f; cu[a][b][d] = 0.f; }

    const int abase = (wm * 64 + g) * 20 + tig;
    const int bbase = tig * 136 + wn * 32 + g;

    float4 ra[4], rb[4];
    // half h covers A k [h*16, h*16+16) (quads 2h,2h+1) and B kp {bk+8h, bk+8h+4}
    #define GU_LDGA(k0, h) do { \
        _Pragma("unroll") \
        for (int j = 0; j < 4; j++) \
            ra[j] = arow ? *(const float4*)(arow + (k0) + (h) * 16 + j * 4) \
                         : make_float4(0.f, 0.f, 0.f, 0.f); \
    } while (0)
    #define GU_LDGB(k0, h) do { \
        _Pragma("unroll") \
        for (int q2 = 0; q2 < 2; q2++) { \
            const int kk = (k0) + 2 * (bk + ((h) * 2 + q2) * 4); \
            rb[q2 * 2 + 0] = *(const float4*)(W + (size_t)kk * (2 * IDIM) + bcol); \
            rb[q2 * 2 + 1] = *(const float4*)(W + (size_t)(kk + 1) * (2 * IDIM) + bcol); \
        } \
    } while (0)
    #define GU_STS(bufi, h) do { \
        _Pragma("unroll") \
        for (int q2 = 0; q2 < 2; q2++) { \
            uint4 u; \
            u.x = pack2(ra[q2 * 2].x, ra[q2 * 2].y); \
            u.y = pack2(ra[q2 * 2].z, ra[q2 * 2].w); \
            u.z = pack2(ra[q2 * 2 + 1].x, ra[q2 * 2 + 1].y); \
            u.w = pack2(ra[q2 * 2 + 1].z, ra[q2 * 2 + 1].w); \
            *(uint4*)&As_[(bufi) * ASZ + tid * 20 + ((h) * 2 + q2) * 4] = u; \
        } \
        _Pragma("unroll") \
        for (int q2 = 0; q2 < 2; q2++) { \
            const int kp = bk + ((h) * 2 + q2) * 4; \
            uint4 u; \
            u.x = pack2(rb[q2 * 2].x, rb[q2 * 2 + 1].x); \
            u.y = pack2(rb[q2 * 2].y, rb[q2 * 2 + 1].y); \
            u.z = pack2(rb[q2 * 2].z, rb[q2 * 2 + 1].z); \
            u.w = pack2(rb[q2 * 2].w, rb[q2 * 2 + 1].w); \
            *(uint4*)&Bs_[(bufi) * BSZ + kp * 136 + bq * 4] = u; \
        } \
    } while (0)
    #define GU_COMP(kf) do { \
        uint32_t a[4][4]; \
        _Pragma("unroll") \
        for (int mf = 0; mf < 4; mf++) { \
            const int o = abase + mf * 320 + (kf) * 8; \
            a[mf][0] = Ab[o];       a[mf][1] = Ab[o + 160]; \
            a[mf][2] = Ab[o + 4];   a[mf][3] = Ab[o + 164]; \
        } \
        _Pragma("unroll") \
        for (int nf = 0; nf < 4; nf++) { \
            const int ob = bbase + (kf) * 1088 + nf * 8; \
            const uint32_t bg0 = Bb[ob],      bg1 = Bb[ob + 544]; \
            const uint32_t bu0 = Bb[ob + 64], bu1 = Bb[ob + 608]; \
            _Pragma("unroll") \
            for (int mf = 0; mf < 4; mf++) { \
                mma16(cg[mf][nf], a[mf], bg0, bg1); \
                mma16(cu[mf][nf], a[mf], bu0, bu1); \
            } \
        } \
    } while (0)

    GU_LDGA(0, 0);  GU_LDGB(0, 0);  GU_STS(0, 0);
    GU_LDGA(0, 1);  GU_LDGB(0, 1);  GU_STS(0, 1);
    __syncthreads();

    const int NC = HDIM / 32;
    for (int c = 0; c < NC; c++) {
        const int buf = c & 1;
        const uint32_t* Ab = As_ + buf * ASZ;
        const uint32_t* Bb = Bs_ + buf * BSZ;
        const bool more = (c + 1 < NC);
        if (more) { GU_LDGA((c + 1) * 32, 0); GU_LDGB((c + 1) * 32, 0); }
        GU_COMP(0);
        if (more) { GU_STS(buf ^ 1, 0); GU_LDGA((c + 1) * 32, 1); GU_LDGB((c + 1) * 32, 1); }
        GU_COMP(1);
        if (more) { GU_STS(buf ^ 1, 1); }
        __syncthreads();
    }
    #undef GU_LDGA
    #undef GU_LDGB
    #undef GU_STS
    #undef GU_COMP

    // epilogue: silu(gate)*up  (C frag: c0=(g,2t) c1=(g,2t+1) c2=(g+8,2t) c3=(g+8,2t+1))
    #pragma unroll
    for (int mf = 0; mf < 4; mf++) {
        #pragma unroll
        for (int nf = 0; nf < 4; nf++) {
            const int row0 = m0 + wm * 64 + mf * 16 + g;
            const int col  = n0 + wn * 32 + nf * 8 + tig * 2;
            if (row0 < n_e) {
                float gv, uv; float2 o;
                gv = cg[mf][nf][0]; uv = cu[mf][nf][0]; o.x = gv / (1.f + __expf(-gv)) * uv;
                gv = cg[mf][nf][1]; uv = cu[mf][nf][1]; o.y = gv / (1.f + __expf(-gv)) * uv;
                *(float2*)(actb + (size_t)row0 * IDIM + col) = o;
            }
            if (row0 + 8 < n_e) {
                float gv, uv; float2 o;
                gv = cg[mf][nf][2]; uv = cu[mf][nf][2]; o.x = gv / (1.f + __expf(-gv)) * uv;
                gv = cg[mf][nf][3]; uv = cu[mf][nf][3]; o.y = gv / (1.f + __expf(-gv)) * uv;
                *(float2*)(actb + (size_t)(row0 + 8) * IDIM + col) = o;
            }
        }
    }
}

// ---------------- down (fp16 mma.sync) ----------------
// 128 thr, 4 warps (2M x 2N). block M=128 x N=128; warp m64 x n64.
template <bool EXPERT>
__global__ void __launch_bounds__(128)
dn_mma(const float* __restrict__ Wd, float* __restrict__ out) {
    const int e = EXPERT ? blockIdx.z : 0;
    const int n_e = EXPERT ? min(g_count[e], CAP) : TTOK;
    const int m0 = blockIdx.y * 128;
    if (m0 >= n_e) return;
    const int n0 = blockIdx.x * 128;

    __shared__ uint32_t As_[2 * ASZ];
    __shared__ uint32_t Bs_[2 * BSZ];

    const int tid = threadIdx.x;
    const int wid = tid >> 5, lane = tid & 31;
    const int g = lane >> 2, tig = lane & 3;
    const int wm = wid & 1, wn = wid >> 1;

    const float* actb = EXPERT ? g_act + (size_t)e * CAP * IDIM : g_shact;
    const float* W = EXPERT ? Wd + (size_t)e * IDIM * HDIM : Wd;

    const float* arow = actb + (size_t)(m0 + tid) * IDIM;
    const int bk = wid, bq = lane;
    const int bcol = n0 + bq * 4;

    float cc[4][8][4];
    #pragma unroll
    for (int a = 0; a < 4; a++)
        #pragma unroll
        for (int b = 0; b < 8; b++)
            #pragma unroll
            for (int d = 0; d < 4; d++) cc[a][b][d] = 0.f;

    const int abase = (wm * 64 + g) * 20 + tig;
    const int bbase = tig * 136 + wn * 64 + g;

    float4 ra[4], rb[4];
    #define DN_LDGA(k0, h) do { \
        _Pragma("unroll") \
        for (int j = 0; j < 4; j++) \
            ra[j] = *(const float4*)(arow + (k0) + (h) * 16 + j * 4); \
    } while (0)
    #define DN_LDGB(k0, h) do { \
        _Pragma("unroll") \
        for (int q2 = 0; q2 < 2; q2++) { \
            const int kk = (k0) + 2 * (bk + ((h) * 2 + q2) * 4); \
            rb[q2 * 2 + 0] = *(const float4*)(W + (size_t)kk * HDIM + bcol); \
            rb[q2 * 2 + 1] = *(const float4*)(W + (size_t)(kk + 1) * HDIM + bcol); \
        } \
    } while (0)
    #define DN_STS(bufi, h) do { \
        _Pragma("unroll") \
        for (int q2 = 0; q2 < 2; q2++) { \
            uint4 u; \
            u.x = pack2(ra[q2 * 2].x, ra[q2 * 2].y); \
            u.y = pack2(ra[q2 * 2].z, ra[q2 * 2].w); \
            u.z = pack2(ra[q2 * 2 + 1].x, ra[q2 * 2 + 1].y); \
            u.w = pack2(ra[q2 * 2 + 1].z, ra[q2 * 2 + 1].w); \
            *(uint4*)&As_[(bufi) * ASZ + tid * 20 + ((h) * 2 + q2) * 4] = u; \
        } \
        _Pragma("unroll") \
        for (int q2 = 0; q2 < 2; q2++) { \
            const int kp = bk + ((h) * 2 + q2) * 4; \
            uint4 u; \
            u.x = pack2(rb[q2 * 2].x, rb[q2 * 2 + 1].x); \
            u.y = pack2(rb[q2 * 2].y, rb[q2 * 2 + 1].y); \
            u.z = pack2(rb[q2 * 2].z, rb[q2 * 2 + 1].z); \
            u.w = pack2(rb[q2 * 2].w, rb[q2 * 2 + 1].w); \
            *(uint4*)&Bs_[(bufi) * BSZ + kp * 136 + bq * 4] = u; \
        } \
    } while (0)
    #define DN_COMP(kf) do { \
        uint32_t a[4][4]; \
        _Pragma("unroll") \
        for (int mf = 0; mf < 4; mf++) { \
            const int o = abase + mf * 320 + (kf) * 8; \
            a[mf][0] = Ab[o];       a[mf][1] = Ab[o + 160]; \
            a[mf][2] = Ab[o + 4];   a[mf][3] = Ab[o + 164]; \
        } \
        _Pragma("unroll") \
        for (int nf = 0; nf < 8; nf++) { \
            const int ob = bbase + (kf) * 1088 + nf * 8; \
            const uint32_t b0 = Bb[ob], b1 = Bb[ob + 544]; \
            _Pragma("unroll") \
            for (int mf = 0; mf < 4; mf++) \
                mma16(cc[mf][nf], a[mf], b0, b1); \
        } \
    } while (0)

    DN_LDGA(0, 0);  DN_LDGB(0, 0);  DN_STS(0, 0);
    DN_LDGA(0, 1);  DN_LDGB(0, 1);  DN_STS(0, 1);
    __syncthreads();

    const int NC = IDIM / 32;
    for (int c = 0; c < NC; c++) {
        const int buf = c & 1;
        const uint32_t* Ab = As_ + buf * ASZ;
        const uint32_t* Bb = Bs_ + buf * BSZ;
        const bool more = (c + 1 < NC);
        if (more) { DN_LDGA((c + 1) * 32, 0); DN_LDGB((c + 1) * 32, 0); }
        DN_COMP(0);
        if (more) { DN_STS(buf ^ 1, 0); DN_LDGA((c + 1) * 32, 1); DN_LDGB((c + 1) * 32, 1); }
        DN_COMP(1);
        if (more) { DN_STS(buf ^ 1, 1); }
        __syncthreads();
    }
    #undef DN_LDGA
    #undef DN_LDGB
    #undef DN_STS
    #undef DN_COMP

    #pragma unroll
    for (int mf = 0; mf < 4; mf++) {
        #pragma unroll
        for (int nf = 0; nf < 8; nf++) {
            const int row0 = m0 + wm * 64 + mf * 16 + g;
            const int col  = n0 + wn * 64 + nf * 8 + tig * 2;
            if (row0 < n_e) {
                float* dst = EXPERT ? (g_dbuf + ((size_t)e * CAP + row0) * HDIM + col)
                                    : (out + (size_t)row0 * HDIM + col);
                *(float2*)dst = make_float2(cc[mf][nf][0], cc[mf][nf][1]);
            }
            if (row0 + 8 < n_e) {
                float* dst = EXPERT ? (g_dbuf + ((size_t)e * CAP + row0 + 8) * HDIM + col)
                                    : (out + (size_t)(row0 + 8) * HDIM + col);
                *(float2*)dst = make_float2(cc[mf][nf][2], cc[mf][nf][3]);
            }
        }
    }
}

// ---------------- combine ----------------
__global__ void __launch_bounds__(256)
combine_kernel(float* __restrict__ out) {
    const int t = blockIdx.x;
    const int i = threadIdx.x;
    float4 acc = ((const float4*)out)[(size_t)t * 256 + i];
    #pragma unroll
    for (int k = 0; k < KTOP; k++) {
        const int e = g_e4[t * KTOP + k];
        const int s = g_s4[t * KTOP + k];
        const float w = g_w4[t * KTOP + k];
        if (s < CAP) {
            const float4 v = ((const float4*)g_dbuf)[((size_t)e * CAP + s) * (HDIM / 4) + i];
            acc.x += w * v.x; acc.y += w * v.y; acc.z += w * v.z; acc.w += w * v.w;
        }
    }
    ((float4*)out)[(size_t)t * 256 + i] = acc;
}

extern "C" void kernel_launch(void* const* d_in, const int* in_sizes, int n_in,
                              void* d_out, int out_size) {
    const float* x   = (const float*)d_in[0];
    const float* gw  = (const float*)d_in[1];
    const float* wgu = (const float*)d_in[2];
    const float* wd  = (const float*)d_in[3];
    const float* sgu = (const float*)d_in[4];
    const float* sd  = (const float*)d_in[5];
    float* out = (float*)d_out;
    (void)in_sizes; (void)n_in; (void)out_size;

    zero_counts_kernel<<<1, 32>>>();
    router_kernel<<<TTOK, 128>>>(x, gw);

    gu_mma<true ><<<dim3(IDIM / 64, CAP / 128, NE), 128>>>(x, wgu);
    gu_mma<false><<<dim3(IDIM / 64, TTOK / 128, 1), 128>>>(x, sgu);

    dn_mma<true ><<<dim3(HDIM / 128, CAP / 128, NE), 128>>>(wd, out);
    dn_mma<false><<<dim3(HDIM / 128, TTOK / 128, 1), 128>>>(sd, out);

    combine_kernel<<<TTOK, 256>>>(out);
}